// round 13
// baseline (speedup 1.0000x reference)
#include <cuda_runtime.h>
#include <cstdint>

// ---- problem constants (match reference) ----
#define BB 4
#define HH 128
#define WW 128
#define SS 72
#define SPS 24          // slices per stack
#define ZS 120          // z_scale
#define ZV 122          // padded depth
#define ST_RATIO 5.0f

#define VOXELS (BB * HH * WW * ZV)      // 7,995,392
#define PIXELS (BB * HH * WW * SS)      // 4,718,592
#define OUT_PER (BB * HH * WW * ZS)     // 7,864,320
#define HWSZ   (HH * WW)                // 16384

#define CHAIN 16                         // h-pixels per thread (u-chain length)

// Interleaved scratch: [2*lin]=N, [2*lin+1]=D. 64 MB, L2-resident.
// Tail cudaMemsetAsync restores the all-zero invariant after every execution.
__device__ __align__(16) float g_acc[2 * VOXELS];

__device__ __forceinline__ void red_add_v2(float* p, float a, float b) {
    asm volatile("red.global.add.v2.f32 [%0], {%1, %2};"
                 :: "l"(p), "f"(a), "f"(b) : "memory");
}

__device__ __forceinline__ void red_add_v4(float* p, float a, float b,
                                           float c, float d) {
    asm volatile("red.global.add.v4.f32 [%0], {%1, %2, %3, %4};"
                 :: "l"(p), "f"(a), "f"(b), "f"(c), "f"(d) : "memory");
}

// Per-axis corner terms: clipped address contributions + masked weights.
struct Axis { int t0, t1; float f0, f1; };

__device__ __forceinline__ Axis axis_eval(float q, int E, int St) {
    float qf = floorf(q);
    int q0 = (int)qf;
    float fr = q - qf;
    int i0 = min(max(q0, 0), E - 1);
    int i1 = min(max(q0 + 1, 0), E - 1);
    Axis a;
    a.t0 = i0 * St;
    a.t1 = i1 * St;
    a.f0 = (q0 >= 0 && q0 < E)      ? (1.0f - fr) : 0.0f;
    a.f1 = (q0 >= -1 && q0 < E - 1) ? fr          : 0.0f;
    return a;
}

// ---------------------------------------------------------------------------
// Splat. Warp = 32 lanes spanning full w (v-merge runs of 32). Each thread
// serially processes a chain of CHAIN h-pixels (u-axis), carrying the u1-row
// of pixel p in registers and merging it into pixel p+1's u0-row on exact
// address equality (sum-preserving; no extra warp communication).
// Axis roles per orientation:
//   axi: u=x(h, stride W*ZV)  v=y(w, stride ZV)  c=z(stride 1)
//   cor: u=x(h, stride W*ZV)  v=z(w, stride 1)   c=y(stride ZV)
//   sag: u=y(h, stride ZV)    v=z(w, stride 1)   c=x(stride W*ZV)
// Red vectorization:
//   axi: the two c-corners are z-adjacent -> per-lane v4 fusion of the c pair.
//   cor/sag: v axis has stride 1, so lo emission addresses are consecutive
//   ACROSS LANES -> lane-pair v4 fusion (lane with even address absorbs its
//   right neighbor's pair via shfl_down; neighbor suppressed via ballot).
// Block = 8 warps = 8 slices for the same (b, CHAIN-h chunk, 32-w chunk).
// Grid = B * 9(sc) * (128/CHAIN)(hc) * 4(wc) = 1152 blocks of 256.
// ---------------------------------------------------------------------------
__global__ __launch_bounds__(256) void splat_kernel(
    const float* __restrict__ vol,    // (B,H,W,S,1)
    const float* __restrict__ trf)    // (B,S,3,4)
{
    __shared__ float sv[CHAIN * 32 * 9];  // [ (h_local*32 + w_local)*9 + s_local ]

    int tid  = threadIdx.x;
    int lane = tid & 31;
    int wid  = tid >> 5;
    int blk  = blockIdx.x;

    int wc = blk & 3;
    int tt = blk >> 2;
    int hc = tt & 7;   tt >>= 3;       // 128/CHAIN = 8 h-chunks
    int sc = tt % 9;
    int b  = tt / 9;

    int h0 = hc * CHAIN, w0 = wc * 32;
    int s  = sc * 8 + wid;            // warp-uniform

    // Stage vol[b, h0..h0+CHAIN-1, w0..w0+31, sc*8..+7] into smem (coalesced,
    // sector-efficient; pad-9 rows for conflict-free readback).
    {
        const float* base = vol + (((size_t)(b * HH + h0) * WW + w0) * SS + sc * 8);
        #pragma unroll
        for (int it = 0; it < CHAIN; it++) {
            int idx = it * 256 + tid;
            int hh = idx >> 8;
            int wl = (idx >> 3) & 31;
            int sl = idx & 7;
            sv[(hh * 32 + wl) * 9 + sl] = base[((size_t)hh * WW + wl) * SS + sl];
        }
    }
    __syncthreads();

    const float* Ap = trf + (size_t)(b * SS + s) * 12;
    float A00 = Ap[0] + 1.0f, A01 = Ap[1],        A02 = Ap[2],         A03 = Ap[3];
    float A10 = Ap[4],        A11 = Ap[5] + 1.0f, A12 = Ap[6],         A13 = Ap[7];
    float A20 = Ap[8],        A21 = Ap[9],        A22 = Ap[10] + 1.0f, A23 = Ap[11];

    int o = s / SPS;                  // warp-uniform orientation
    float tc = (float)(s % SPS) * ST_RATIO;
    int w = w0 + lane;
    int bb = b * HH * WW * ZV;

    // carry per c-corner: pixel p's u1-row awaiting merge with p+1's u0-row
    int   cLoA[2] = { -1, -1 };
    float cLoN[2], cLoD[2];
    int   cHiA[2];
    float cHiN[2], cHiD[2];
    bool  cHiS[2] = { false, false };

    for (int p = 0; p < CHAIN; p++) {
        int h = h0 + p;
        float v = sv[(p * 32 + lane) * 9 + wid];   // conflict-free (stride 9)

        float bx, by, bz;
        if (o == 0)      { bx = (float)h; by = (float)w; bz = tc; }
        else if (o == 1) { bx = (float)h; by = tc;       bz = (float)w; }
        else             { bx = tc;       by = (float)h; bz = (float)w; }

        float x = A00 * bx + A01 * by + A02 * bz + A03;
        float y = A10 * bx + A11 * by + A12 * bz + A13;
        float z = A20 * bx + A21 * by + A22 * bz + A23 + 1.0f;

        Axis U, V, C;
        if (o == 0) {
            U = axis_eval(x, HH, WW * ZV);
            V = axis_eval(y, WW, ZV);
            C = axis_eval(z, ZV, 1);
        } else if (o == 1) {
            U = axis_eval(x, HH, WW * ZV);
            V = axis_eval(z, ZV, 1);
            C = axis_eval(y, WW, ZV);
        } else {
            U = axis_eval(y, WW, ZV);
            V = axis_eval(z, ZV, 1);
            C = axis_eval(x, HH, WW * ZV);
        }

        // lo-row emission candidates per c (filled below, emitted after)
        int   eL[2];
        float eN[2], eD[2];

        #pragma unroll
        for (int c = 0; c < 2; c++) {
            int   ct = c ? C.t1 : C.t0;
            float fc = c ? C.f1 : C.f0;

            int   rL[2], rH[2];
            float rAccN[2], rAccD[2], rHiN[2], rHiD[2];
            bool  rS[2];

            // v-merge along the 32-lane w run, for both u rows
            #pragma unroll
            for (int r = 0; r < 2; r++) {
                int   ut = r ? U.t1 : U.t0;
                float fu = r ? U.f1 : U.f0;
                int L  = bb + ut + V.t0 + ct;
                int Hh = bb + ut + V.t1 + ct;
                float wlo = fu * V.f0 * fc;
                float whi = fu * V.f1 * fc;
                float NhiV = whi * v;

                float nbN = __shfl_up_sync(0xffffffffu, NhiV, 1);
                float nbD = __shfl_up_sync(0xffffffffu, whi, 1);
                int   nbH = __shfl_up_sync(0xffffffffu, Hh, 1);
                bool mrg = (lane > 0) && (nbH == L);
                unsigned bal = __ballot_sync(0xffffffffu, mrg);
                bool absorbed = (bal & (2u << lane)) != 0u;  // lane31 -> false

                rL[r]    = L;
                rAccN[r] = wlo * v + (mrg ? nbN : 0.0f);
                rAccD[r] = wlo     + (mrg ? nbD : 0.0f);
                rH[r]    = Hh;
                rHiN[r]  = NhiV;
                rHiD[r]  = whi;
                rS[r]    = !absorbed;
            }

            // u-chain: absorb previous pixel's u1-row (carry) into this u0-row
            if (cLoA[c] >= 0) {
                if (cLoA[c] == rL[0]) {
                    rAccN[0] += cLoN[c];
                    rAccD[0] += cLoD[c];
                } else {
                    red_add_v2(&g_acc[2 * cLoA[c]], cLoN[c], cLoD[c]);
                }
                if (cHiS[c]) {
                    if (rS[0] && cHiA[c] == rH[0]) {
                        rHiN[0] += cHiN[c];
                        rHiD[0] += cHiD[c];
                    } else {
                        red_add_v2(&g_acc[2 * cHiA[c]], cHiN[c], cHiD[c]);
                    }
                }
            }

            // record u0-row lo emission; emit surviving u0-row hi now (rare)
            eL[c] = rL[0]; eN[c] = rAccN[0]; eD[c] = rAccD[0];
            if (rS[0])
                red_add_v2(&g_acc[2 * rH[0]], rHiN[0], rHiD[0]);

            // u1-row becomes the new carry
            cLoA[c] = rL[1]; cLoN[c] = rAccN[1]; cLoD[c] = rAccD[1];
            cHiA[c] = rH[1]; cHiN[c] = rHiN[1]; cHiD[c] = rHiD[1];
            cHiS[c] = rS[1];
        }

        // ---- emit the two lo-rows ----
        if (o == 0) {
            // axi: c-corners z-adjacent -> per-lane v4 fusion
            bool fuse = (eL[1] == eL[0] + 1) && ((eL[0] & 1) == 0);
            if (fuse) {
                red_add_v4(&g_acc[2 * eL[0]], eN[0], eD[0], eN[1], eD[1]);
            } else {
                red_add_v2(&g_acc[2 * eL[0]], eN[0], eD[0]);
                red_add_v2(&g_acc[2 * eL[1]], eN[1], eD[1]);
            }
        } else {
            // cor/sag: lo addresses consecutive ACROSS LANES -> lane-pair v4.
            // Lane with even address fuses its right neighbor's pair; the
            // neighbor (ballot-detected) suppresses its own red. Parity
            // guarantees a lane cannot both fuse and be fused.
            #pragma unroll
            for (int c = 0; c < 2; c++) {
                int   nL = __shfl_down_sync(0xffffffffu, eL[c], 1);
                float nN = __shfl_down_sync(0xffffffffu, eN[c], 1);
                float nD = __shfl_down_sync(0xffffffffu, eD[c], 1);
                bool fuse = (lane < 31) && ((eL[c] & 1) == 0) && (nL == eL[c] + 1);
                unsigned bal = __ballot_sync(0xffffffffu, fuse);
                bool absorbed = (lane > 0) && ((bal >> (lane - 1)) & 1u);
                if (fuse)
                    red_add_v4(&g_acc[2 * eL[c]], eN[c], eD[c], nN, nD);
                else if (!absorbed)
                    red_add_v2(&g_acc[2 * eL[c]], eN[c], eD[c]);
            }
        }
    }

    // flush remaining carries
    #pragma unroll
    for (int c = 0; c < 2; c++) {
        if (cLoA[c] >= 0) {
            red_add_v2(&g_acc[2 * cLoA[c]], cLoN[c], cLoD[c]);
            if (cHiS[c])
                red_add_v2(&g_acc[2 * cHiA[c]], cHiN[c], cHiD[c]);
        }
    }
}

// ---------------------------------------------------------------------------
// Finalize: crop z[1:1+ZS], split interleaved N/D, where(D<=0, 1, D).
// One warp per (b,h,w) column: strided passes of 32 z (last predicated).
// __ldcs on acc (dead after read; memset rewrites), __stcs on out (streaming,
// don't thrash the L2-resident accumulator).
// Grid = HWSZ*BB/8 = 8192 blocks of 256 (8 warps = 8 columns per block).
// ---------------------------------------------------------------------------
__global__ __launch_bounds__(256) void finalize_kernel(float* __restrict__ out)
{
    int lane = threadIdx.x & 31;
    int col  = blockIdx.x * 8 + (threadIdx.x >> 5);   // global hwb column

    const float2* acc = reinterpret_cast<const float2*>(g_acc);
    int lin = col * ZV + 1;
    int oj  = col * ZS;

    float2 p0 = __ldcs(&acc[lin + lane]);
    float2 p1 = __ldcs(&acc[lin + lane + 32]);
    float2 p2 = __ldcs(&acc[lin + lane + 64]);
    float2 p3 = (lane < 24) ? __ldcs(&acc[lin + lane + 96]) : make_float2(0.f, 0.f);

    __stcs(&out[oj + lane],      p0.x);
    __stcs(&out[oj + lane + 32], p1.x);
    __stcs(&out[oj + lane + 64], p2.x);
    __stcs(&out[OUT_PER + oj + lane],      (p0.y > 0.0f) ? p0.y : 1.0f);
    __stcs(&out[OUT_PER + oj + lane + 32], (p1.y > 0.0f) ? p1.y : 1.0f);
    __stcs(&out[OUT_PER + oj + lane + 64], (p2.y > 0.0f) ? p2.y : 1.0f);
    if (lane < 24) {
        __stcs(&out[oj + lane + 96],           p3.x);
        __stcs(&out[OUT_PER + oj + lane + 96], (p3.y > 0.0f) ? p3.y : 1.0f);
    }
}

// ---------------------------------------------------------------------------
extern "C" void kernel_launch(void* const* d_in, const int* in_sizes, int n_in,
                              void* d_out, int out_size)
{
    const float* vol = (const float*)d_in[0];
    const float* trf = (const float*)d_in[1];
    float* out = (float*)d_out;

    splat_kernel<<<BB * 9 * (HH / CHAIN) * 4, 256>>>(vol, trf);
    finalize_kernel<<<(HWSZ * BB) / 8, 256>>>(out);

    // Restore the all-zero invariant for the next replay; also leaves the
    // accumulator zeroed and warm in L2 for the next splat.
    void* acc_ptr = nullptr;
    cudaGetSymbolAddress(&acc_ptr, g_acc);
    cudaMemsetAsync(acc_ptr, 0, sizeof(float) * 2 * VOXELS, 0);
}

// round 14
// speedup vs baseline: 1.1346x; 1.1346x over previous
#include <cuda_runtime.h>
#include <cstdint>

// ---- problem constants (match reference) ----
#define BB 4
#define HH 128
#define WW 128
#define SS 72
#define SPS 24          // slices per stack
#define ZS 120          // z_scale
#define ZV 122          // padded depth
#define ST_RATIO 5.0f

#define VOXELS (BB * HH * WW * ZV)      // 7,995,392
#define PIXELS (BB * HH * WW * SS)      // 4,718,592
#define OUT_PER (BB * HH * WW * ZS)     // 7,864,320
#define HWSZ   (HH * WW)                // 16384

#define CHAIN 16                         // h-pixels per thread (u-chain length)

// Interleaved scratch: [2*lin]=N, [2*lin+1]=D. 64 MB, L2-resident.
// Tail cudaMemsetAsync restores the all-zero invariant after every execution.
__device__ __align__(16) float g_acc[2 * VOXELS];

__device__ __forceinline__ void red_add_v2(float* p, float a, float b) {
    asm volatile("red.global.add.v2.f32 [%0], {%1, %2};"
                 :: "l"(p), "f"(a), "f"(b) : "memory");
}

__device__ __forceinline__ void red_add_v4(float* p, float a, float b,
                                           float c, float d) {
    asm volatile("red.global.add.v4.f32 [%0], {%1, %2, %3, %4};"
                 :: "l"(p), "f"(a), "f"(b), "f"(c), "f"(d) : "memory");
}

// Per-axis corner terms: clipped address contributions + masked weights.
struct Axis { int t0, t1; float f0, f1; };

__device__ __forceinline__ Axis axis_eval(float q, int E, int St) {
    float qf = floorf(q);
    int q0 = (int)qf;
    float fr = q - qf;
    int i0 = min(max(q0, 0), E - 1);
    int i1 = min(max(q0 + 1, 0), E - 1);
    Axis a;
    a.t0 = i0 * St;
    a.t1 = i1 * St;
    a.f0 = (q0 >= 0 && q0 < E)      ? (1.0f - fr) : 0.0f;
    a.f1 = (q0 >= -1 && q0 < E - 1) ? fr          : 0.0f;
    return a;
}

// ---------------------------------------------------------------------------
// Splat. Warp = 32 lanes spanning full w (v-merge runs of 32). Each thread
// serially processes a chain of CHAIN h-pixels (u-axis), carrying the u1-row
// of pixel p in registers and merging it into pixel p+1's u0-row on exact
// address equality (sum-preserving; no extra warp communication).
// Axis roles per orientation:
//   axi: u=x(h, stride W*ZV)  v=y(w, stride ZV)  c=z(stride 1)
//   cor: u=x(h, stride W*ZV)  v=z(w, stride 1)   c=y(stride ZV)
//   sag: u=y(h, stride ZV)    v=z(w, stride 1)   c=x(stride W*ZV)
// Red vectorization: axi's two c-corners are z-adjacent -> lane-uniform v4
// fusion of the c pair (lane-pair fusion across lanes was tried and REGRESSED
// — half-populated v4 wavefronts don't beat full-warp v2; do not reintroduce).
// Block = 8 warps = 8 slices for the same (b, CHAIN-h chunk, 32-w chunk).
// Grid = B * 9(sc) * (128/CHAIN)(hc) * 4(wc) = 1152 blocks of 256.
// ---------------------------------------------------------------------------
__global__ __launch_bounds__(256) void splat_kernel(
    const float* __restrict__ vol,    // (B,H,W,S,1)
    const float* __restrict__ trf)    // (B,S,3,4)
{
    __shared__ float sv[CHAIN * 32 * 9];  // [ (h_local*32 + w_local)*9 + s_local ]

    int tid  = threadIdx.x;
    int lane = tid & 31;
    int wid  = tid >> 5;
    int blk  = blockIdx.x;

    int wc = blk & 3;
    int tt = blk >> 2;
    int hc = tt & 7;   tt >>= 3;       // 128/CHAIN = 8 h-chunks
    int sc = tt % 9;
    int b  = tt / 9;

    int h0 = hc * CHAIN, w0 = wc * 32;
    int s  = sc * 8 + wid;            // warp-uniform

    // Stage vol[b, h0..h0+CHAIN-1, w0..w0+31, sc*8..+7] into smem (coalesced,
    // sector-efficient; pad-9 rows for conflict-free readback).
    {
        const float* base = vol + (((size_t)(b * HH + h0) * WW + w0) * SS + sc * 8);
        #pragma unroll
        for (int it = 0; it < CHAIN; it++) {
            int idx = it * 256 + tid;
            int hh = idx >> 8;
            int wl = (idx >> 3) & 31;
            int sl = idx & 7;
            sv[(hh * 32 + wl) * 9 + sl] = base[((size_t)hh * WW + wl) * SS + sl];
        }
    }
    __syncthreads();

    const float* Ap = trf + (size_t)(b * SS + s) * 12;
    float A00 = Ap[0] + 1.0f, A01 = Ap[1],        A02 = Ap[2],         A03 = Ap[3];
    float A10 = Ap[4],        A11 = Ap[5] + 1.0f, A12 = Ap[6],         A13 = Ap[7];
    float A20 = Ap[8],        A21 = Ap[9],        A22 = Ap[10] + 1.0f, A23 = Ap[11];

    int o = s / SPS;                  // warp-uniform orientation
    float tc = (float)(s % SPS) * ST_RATIO;
    int w = w0 + lane;
    int bb = b * HH * WW * ZV;

    // carry per c-corner: pixel p's u1-row awaiting merge with p+1's u0-row
    int   cLoA[2] = { -1, -1 };
    float cLoN[2], cLoD[2];
    int   cHiA[2];
    float cHiN[2], cHiD[2];
    bool  cHiS[2] = { false, false };

    for (int p = 0; p < CHAIN; p++) {
        int h = h0 + p;
        float v = sv[(p * 32 + lane) * 9 + wid];   // conflict-free (stride 9)
        float nbV = __shfl_up_sync(0xffffffffu, v, 1);  // neighbor's intensity
                                                        // (shared by all 4 combos)

        float bx, by, bz;
        if (o == 0)      { bx = (float)h; by = (float)w; bz = tc; }
        else if (o == 1) { bx = (float)h; by = tc;       bz = (float)w; }
        else             { bx = tc;       by = (float)h; bz = (float)w; }

        float x = A00 * bx + A01 * by + A02 * bz + A03;
        float y = A10 * bx + A11 * by + A12 * bz + A13;
        float z = A20 * bx + A21 * by + A22 * bz + A23 + 1.0f;

        Axis U, V, C;
        if (o == 0) {
            U = axis_eval(x, HH, WW * ZV);
            V = axis_eval(y, WW, ZV);
            C = axis_eval(z, ZV, 1);
        } else if (o == 1) {
            U = axis_eval(x, HH, WW * ZV);
            V = axis_eval(z, ZV, 1);
            C = axis_eval(y, WW, ZV);
        } else {
            U = axis_eval(y, WW, ZV);
            V = axis_eval(z, ZV, 1);
            C = axis_eval(x, HH, WW * ZV);
        }

        // lo-row emission candidates per c (filled below, emitted after)
        int   eL[2];
        float eN[2], eD[2];

        #pragma unroll
        for (int c = 0; c < 2; c++) {
            int   ct = c ? C.t1 : C.t0;
            float fc = c ? C.f1 : C.f0;

            int   rL[2], rH[2];
            float rAccN[2], rAccD[2], rHiN[2], rHiD[2];
            bool  rS[2];

            // v-merge along the 32-lane w run, for both u rows.
            // Neighbor numerator reconstructed as nbD*nbV (bit-identical to
            // shfl of whi*v) — saves one shfl per combo.
            #pragma unroll
            for (int r = 0; r < 2; r++) {
                int   ut = r ? U.t1 : U.t0;
                float fu = r ? U.f1 : U.f0;
                int L  = bb + ut + V.t0 + ct;
                int Hh = bb + ut + V.t1 + ct;
                float wlo = fu * V.f0 * fc;
                float whi = fu * V.f1 * fc;
                float NhiV = whi * v;

                float nbD = __shfl_up_sync(0xffffffffu, whi, 1);
                int   nbH = __shfl_up_sync(0xffffffffu, Hh, 1);
                float nbN = nbD * nbV;
                bool mrg = (lane > 0) && (nbH == L);
                unsigned bal = __ballot_sync(0xffffffffu, mrg);
                bool absorbed = (bal & (2u << lane)) != 0u;  // lane31 -> false

                rL[r]    = L;
                rAccN[r] = wlo * v + (mrg ? nbN : 0.0f);
                rAccD[r] = wlo     + (mrg ? nbD : 0.0f);
                rH[r]    = Hh;
                rHiN[r]  = NhiV;
                rHiD[r]  = whi;
                rS[r]    = !absorbed;
            }

            // u-chain: absorb previous pixel's u1-row (carry) into this u0-row
            if (cLoA[c] >= 0) {
                if (cLoA[c] == rL[0]) {
                    rAccN[0] += cLoN[c];
                    rAccD[0] += cLoD[c];
                } else {
                    red_add_v2(&g_acc[2 * cLoA[c]], cLoN[c], cLoD[c]);
                }
                if (cHiS[c]) {
                    if (rS[0] && cHiA[c] == rH[0]) {
                        rHiN[0] += cHiN[c];
                        rHiD[0] += cHiD[c];
                    } else {
                        red_add_v2(&g_acc[2 * cHiA[c]], cHiN[c], cHiD[c]);
                    }
                }
            }

            // record u0-row lo emission; emit surviving u0-row hi now (rare)
            eL[c] = rL[0]; eN[c] = rAccN[0]; eD[c] = rAccD[0];
            if (rS[0])
                red_add_v2(&g_acc[2 * rH[0]], rHiN[0], rHiD[0]);

            // u1-row becomes the new carry
            cLoA[c] = rL[1]; cLoN[c] = rAccN[1]; cLoD[c] = rAccD[1];
            cHiA[c] = rH[1]; cHiN[c] = rHiN[1]; cHiD[c] = rHiD[1];
            cHiS[c] = rS[1];
        }

        // emit the two lo-rows; axi fuses adjacent c-pairs into one v4 red
        if (o == 0) {
            bool fuse = (eL[1] == eL[0] + 1) && ((eL[0] & 1) == 0);
            if (fuse) {
                red_add_v4(&g_acc[2 * eL[0]], eN[0], eD[0], eN[1], eD[1]);
            } else {
                red_add_v2(&g_acc[2 * eL[0]], eN[0], eD[0]);
                red_add_v2(&g_acc[2 * eL[1]], eN[1], eD[1]);
            }
        } else {
            red_add_v2(&g_acc[2 * eL[0]], eN[0], eD[0]);
            red_add_v2(&g_acc[2 * eL[1]], eN[1], eD[1]);
        }
    }

    // flush remaining carries
    #pragma unroll
    for (int c = 0; c < 2; c++) {
        if (cLoA[c] >= 0) {
            red_add_v2(&g_acc[2 * cLoA[c]], cLoN[c], cLoD[c]);
            if (cHiS[c])
                red_add_v2(&g_acc[2 * cHiA[c]], cHiN[c], cHiD[c]);
        }
    }
}

// ---------------------------------------------------------------------------
// Finalize: crop z[1:1+ZS], split interleaved N/D, where(D<=0, 1, D).
// One warp handles TWO (b,h,w) columns (ILP=8) in strided passes of 32 z
// (last pass predicated). __ldcs on acc (dead after read; memset rewrites),
// __stcs on out (streaming, don't thrash the L2-resident accumulator).
// Grid = HWSZ*BB/16 = 4096 blocks of 256 (8 warps x 2 columns per block).
// ---------------------------------------------------------------------------
__global__ __launch_bounds__(256) void finalize_kernel(float* __restrict__ out)
{
    int lane = threadIdx.x & 31;
    int col  = (blockIdx.x * 8 + (threadIdx.x >> 5)) * 2;  // first of 2 columns

    const float2* acc = reinterpret_cast<const float2*>(g_acc);

    int linA = col * ZV + 1;
    int linB = linA + ZV;
    int ojA  = col * ZS;
    int ojB  = ojA + ZS;

    float2 a0 = __ldcs(&acc[linA + lane]);
    float2 a1 = __ldcs(&acc[linA + lane + 32]);
    float2 a2 = __ldcs(&acc[linA + lane + 64]);
    float2 a3 = (lane < 24) ? __ldcs(&acc[linA + lane + 96]) : make_float2(0.f, 0.f);
    float2 b0 = __ldcs(&acc[linB + lane]);
    float2 b1 = __ldcs(&acc[linB + lane + 32]);
    float2 b2 = __ldcs(&acc[linB + lane + 64]);
    float2 b3 = (lane < 24) ? __ldcs(&acc[linB + lane + 96]) : make_float2(0.f, 0.f);

    __stcs(&out[ojA + lane],      a0.x);
    __stcs(&out[ojA + lane + 32], a1.x);
    __stcs(&out[ojA + lane + 64], a2.x);
    __stcs(&out[ojB + lane],      b0.x);
    __stcs(&out[ojB + lane + 32], b1.x);
    __stcs(&out[ojB + lane + 64], b2.x);
    __stcs(&out[OUT_PER + ojA + lane],      (a0.y > 0.0f) ? a0.y : 1.0f);
    __stcs(&out[OUT_PER + ojA + lane + 32], (a1.y > 0.0f) ? a1.y : 1.0f);
    __stcs(&out[OUT_PER + ojA + lane + 64], (a2.y > 0.0f) ? a2.y : 1.0f);
    __stcs(&out[OUT_PER + ojB + lane],      (b0.y > 0.0f) ? b0.y : 1.0f);
    __stcs(&out[OUT_PER + ojB + lane + 32], (b1.y > 0.0f) ? b1.y : 1.0f);
    __stcs(&out[OUT_PER + ojB + lane + 64], (b2.y > 0.0f) ? b2.y : 1.0f);
    if (lane < 24) {
        __stcs(&out[ojA + lane + 96],           a3.x);
        __stcs(&out[ojB + lane + 96],           b3.x);
        __stcs(&out[OUT_PER + ojA + lane + 96], (a3.y > 0.0f) ? a3.y : 1.0f);
        __stcs(&out[OUT_PER + ojB + lane + 96], (b3.y > 0.0f) ? b3.y : 1.0f);
    }
}

// ---------------------------------------------------------------------------
extern "C" void kernel_launch(void* const* d_in, const int* in_sizes, int n_in,
                              void* d_out, int out_size)
{
    const float* vol = (const float*)d_in[0];
    const float* trf = (const float*)d_in[1];
    float* out = (float*)d_out;

    splat_kernel<<<BB * 9 * (HH / CHAIN) * 4, 256>>>(vol, trf);
    finalize_kernel<<<(HWSZ * BB) / 16, 256>>>(out);

    // Restore the all-zero invariant for the next replay; also leaves the
    // accumulator zeroed and warm in L2 for the next splat.
    void* acc_ptr = nullptr;
    cudaGetSymbolAddress(&acc_ptr, g_acc);
    cudaMemsetAsync(acc_ptr, 0, sizeof(float) * 2 * VOXELS, 0);
}